// round 17
// baseline (speedup 1.0000x reference)
#include <cuda_runtime.h>
#include <cuda_fp16.h>
#include <cstdint>

#define N_NODES 50000
#define N_EDGES 800000
#define D 128
#define R 4
#define NSEG (N_NODES * R)      // 200000
#define NLAYER 3
#define KTOT 640                // R*D + D
#define MPAD 50048              // 391 * 128
#define NTILES 391
#define NCHUNK 10               // K chunks of 64 fp16 (128B rows)

// ---------------- static device scratch ----------------
__device__ __align__(16) __half g_ah[(size_t)MPAD * KTOT];        // A fp16 [node][640]
__device__ __align__(16) __half g_bh[(size_t)NLAYER * D * KTOT];  // B fp16 [l][n][k]
__device__ float g_x1[(size_t)N_NODES * D];
__device__ float g_x2[(size_t)N_NODES * D];
__device__ int   g_cnt[NSEG];     // zero-initialized; re-zeroed by k_scan23 each run
__device__ int   g_off[NSEG + 1];
__device__ int   g_cursor[NSEG];
__device__ int   g_bsum[256];
__device__ int   g_srcs[N_EDGES];

// ---------------- helpers ----------------
__device__ __forceinline__ uint32_t smem_to_u32(const void* p) {
    uint32_t a;
    asm("{ .reg .u64 t; cvta.to.shared.u64 t, %1; cvt.u32.u64 %0, t; }"
        : "=r"(a) : "l"(p));
    return a;
}

#define CP16(sm, gp) \
    asm volatile("cp.async.cg.shared.global [%0], [%1], 16;" :: "r"(sm), "l"(gp))

__device__ __forceinline__ void ldsm_x4(uint32_t* f, uint32_t addr) {
    asm volatile("ldmatrix.sync.aligned.m8n8.x4.shared.b16 {%0,%1,%2,%3}, [%4];"
                 : "=r"(f[0]), "=r"(f[1]), "=r"(f[2]), "=r"(f[3]) : "r"(addr));
}

__device__ __forceinline__ void mma16816(float* d, const uint32_t* a,
                                         uint32_t b0, uint32_t b1) {
    asm volatile(
        "mma.sync.aligned.m16n8k16.row.col.f32.f16.f16.f32 "
        "{%0,%1,%2,%3}, {%4,%5,%6,%7}, {%8,%9}, {%0,%1,%2,%3};"
        : "+f"(d[0]), "+f"(d[1]), "+f"(d[2]), "+f"(d[3])
        : "r"(a[0]), "r"(a[1]), "r"(a[2]), "r"(a[3]), "r"(b0), "r"(b1));
}

// ---------------- CSR build ----------------
__global__ void k_hist(const int* __restrict__ dst, const int* __restrict__ et) {
    int e = blockIdx.x * blockDim.x + threadIdx.x;
    if (e < N_EDGES) atomicAdd(&g_cnt[dst[e] * R + et[e]], 1);
}

__global__ void k_scan1() {
    __shared__ int sh[1024];
    int t = threadIdx.x;
    int i = blockIdx.x * 1024 + t;
    int v = (i < NSEG) ? g_cnt[i] : 0;
    sh[t] = v;
    __syncthreads();
    for (int d = 1; d < 1024; d <<= 1) {
        int add = (t >= d) ? sh[t - d] : 0;
        __syncthreads();
        sh[t] += add;
        __syncthreads();
    }
    if (i < NSEG) g_off[i] = sh[t] - v;
    if (t == 1023) g_bsum[blockIdx.x] = sh[1023];
}

// fused scan2+scan3; also re-zeroes g_cnt for the next graph replay.
__global__ void k_scan23(int nb) {
    __shared__ int sh[256];
    int t = threadIdx.x;
    if (t < 256) sh[t] = (t < nb) ? g_bsum[t] : 0;
    __syncthreads();
    for (int d = 1; d < 256; d <<= 1) {
        int add = 0;
        if (t < 256 && t >= d) add = sh[t - d];
        __syncthreads();
        if (t < 256) sh[t] += add;
        __syncthreads();
    }
    int boff = (blockIdx.x > 0) ? sh[blockIdx.x - 1] : 0;
    int i = blockIdx.x * 1024 + t;
    if (i < NSEG) {
        int o = g_off[i] + boff;
        g_off[i] = o;
        g_cursor[i] = o;
        g_cnt[i] = 0;                 // self-clean for next replay
    }
    if (i == 0) g_off[NSEG] = N_EDGES;
}

__global__ void k_scatter(const int* __restrict__ src, const int* __restrict__ dst,
                          const int* __restrict__ et) {
    int e = blockIdx.x * blockDim.x + threadIdx.x;
    if (e < N_EDGES) {
        int seg = dst[e] * R + et[e];
        int pos = atomicAdd(&g_cursor[seg], 1);
        g_srcs[pos] = src[e];
    }
}

// ---------------- fused prep: weight transpose + fp16, and layer-0 self-cols ----------------
// index space: [0, NLAYER*D*KTOT) -> weights; [NLAYER*D*KTOT, +N_NODES*32) -> convx warps
#define NW (NLAYER * D * KTOT)   // 245760
__global__ void k_prep(const float* __restrict__ W, const float* __restrict__ root,
                       const float* __restrict__ x) {
    int i = blockIdx.x * 256 + threadIdx.x;
    if (i < NW) {
        int k = i % KTOT;
        int t = i / KTOT;
        int n = t % D;
        int l = t / D;
        float w;
        if (k < 512) {
            int r = k >> 7, din = k & 127;
            w = W[(((size_t)l * R + r) * D + din) * D + n];
        } else {
            w = root[((size_t)l * D + (k - 512)) * D + n];
        }
        g_bh[i] = __float2half_rn(w);
    } else {
        int u = i - NW;                 // warp-unit index: row = u/32, lane = u%32
        int row = u >> 5;
        if (row >= N_NODES) return;
        int lane = u & 31;
        float4 v = *reinterpret_cast<const float4*>(x + (size_t)row * D + lane * 4);
        __half h[4];
        h[0] = __float2half_rn(v.x);
        h[1] = __float2half_rn(v.y);
        h[2] = __float2half_rn(v.z);
        h[3] = __float2half_rn(v.w);
        size_t o = (size_t)row * KTOT + 512 + lane * 4;
        *reinterpret_cast<uint2*>(&g_ah[o]) = *reinterpret_cast<uint2*>(h);
    }
}

// ---------------- aggregation: node per warp, 4 interleaved relation chains ----------------
__global__ void k_agg() {
    int node = blockIdx.x * 8 + (threadIdx.x >> 5);
    if (node >= N_NODES) return;
    int lane = threadIdx.x & 31;
    int base = node * 4;
    int j0 = g_off[base + 0], e0 = g_off[base + 1];
    int j1 = e0,              e1 = g_off[base + 2];
    int j2 = e1,              e2 = g_off[base + 3];
    int j3 = e2,              e3 = g_off[base + 4];
    int c0 = e0 - j0, c1 = e1 - j1, c2 = e2 - j2, c3 = e3 - j3;

    float acc[4][4];
#pragma unroll
    for (int r = 0; r < 4; r++)
#pragma unroll
        for (int j = 0; j < 4; j++) acc[r][j] = 0.f;

    for (;;) {
        bool a0 = j0 < e0, a1 = j1 < e1, a2 = j2 < e2, a3 = j3 < e3;
        if (!(a0 | a1 | a2 | a3)) break;
        // inactive chains read g_srcs[0]/row 0 -> L1-resident, ~free; masked to 0
        int s0 = a0 ? g_srcs[j0] : 0;
        int s1 = a1 ? g_srcs[j1] : 0;
        int s2 = a2 ? g_srcs[j2] : 0;
        int s3 = a3 ? g_srcs[j3] : 0;
        int sn0 = a0 ? s0 : 0, sn1 = a1 ? s1 : 0, sn2 = a2 ? s2 : 0, sn3 = a3 ? s3 : 0;
        uint2 r0 = *reinterpret_cast<const uint2*>(&g_ah[(size_t)sn0 * KTOT + 512 + lane * 4]);
        uint2 r1 = *reinterpret_cast<const uint2*>(&g_ah[(size_t)sn1 * KTOT + 512 + lane * 4]);
        uint2 r2 = *reinterpret_cast<const uint2*>(&g_ah[(size_t)sn2 * KTOT + 512 + lane * 4]);
        uint2 r3 = *reinterpret_cast<const uint2*>(&g_ah[(size_t)sn3 * KTOT + 512 + lane * 4]);
        float m0 = a0 ? 1.f : 0.f, m1 = a1 ? 1.f : 0.f;
        float m2 = a2 ? 1.f : 0.f, m3 = a3 ? 1.f : 0.f;
        {
            float2 f0 = __half22float2(*reinterpret_cast<__half2*>(&r0.x));
            float2 f1 = __half22float2(*reinterpret_cast<__half2*>(&r0.y));
            acc[0][0] = fmaf(m0, f0.x, acc[0][0]); acc[0][1] = fmaf(m0, f0.y, acc[0][1]);
            acc[0][2] = fmaf(m0, f1.x, acc[0][2]); acc[0][3] = fmaf(m0, f1.y, acc[0][3]);
        }
        {
            float2 f0 = __half22float2(*reinterpret_cast<__half2*>(&r1.x));
            float2 f1 = __half22float2(*reinterpret_cast<__half2*>(&r1.y));
            acc[1][0] = fmaf(m1, f0.x, acc[1][0]); acc[1][1] = fmaf(m1, f0.y, acc[1][1]);
            acc[1][2] = fmaf(m1, f1.x, acc[1][2]); acc[1][3] = fmaf(m1, f1.y, acc[1][3]);
        }
        {
            float2 f0 = __half22float2(*reinterpret_cast<__half2*>(&r2.x));
            float2 f1 = __half22float2(*reinterpret_cast<__half2*>(&r2.y));
            acc[2][0] = fmaf(m2, f0.x, acc[2][0]); acc[2][1] = fmaf(m2, f0.y, acc[2][1]);
            acc[2][2] = fmaf(m2, f1.x, acc[2][2]); acc[2][3] = fmaf(m2, f1.y, acc[2][3]);
        }
        {
            float2 f0 = __half22float2(*reinterpret_cast<__half2*>(&r3.x));
            float2 f1 = __half22float2(*reinterpret_cast<__half2*>(&r3.y));
            acc[3][0] = fmaf(m3, f0.x, acc[3][0]); acc[3][1] = fmaf(m3, f0.y, acc[3][1]);
            acc[3][2] = fmaf(m3, f1.x, acc[3][2]); acc[3][3] = fmaf(m3, f1.y, acc[3][3]);
        }
        j0 += a0; j1 += a1; j2 += a2; j3 += a3;
    }

    int cnts[4] = {c0, c1, c2, c3};
#pragma unroll
    for (int r = 0; r < 4; r++) {
        float inv = (cnts[r] > 0) ? 1.0f / (float)cnts[r] : 0.0f;
        __half h[4];
        h[0] = __float2half_rn(acc[r][0] * inv);
        h[1] = __float2half_rn(acc[r][1] * inv);
        h[2] = __float2half_rn(acc[r][2] * inv);
        h[3] = __float2half_rn(acc[r][3] * inv);
        *reinterpret_cast<uint2*>(&g_ah[(size_t)node * KTOT + r * 128 + lane * 4]) =
            *reinterpret_cast<uint2*>(h);
    }
}

// ---------------- HMMA GEMM + fused relu/residual/LayerNorm, occupancy-2 ----------------
// smem: [0:512) bias, [512:1024) gamma, [1024:1536) beta
//       A tiles (double buffered): 2048 + buf*16384
//       B tile (single buffered):  2048 + 32768
//       LN row partials (post-mainloop, reuse tile area): 2048 sSum[128][2], 3072 sSq[128][2]
#define SMEM_DYN (2048 + 2 * 16384 + 16384)   // 51200 -> 2 CTAs/SM

__global__ void __launch_bounds__(256, 2) k_gemm(int layer, const float* __restrict__ bias,
                                                 const float* __restrict__ gamma,
                                                 const float* __restrict__ beta,
                                                 const float* __restrict__ xin,
                                                 float* __restrict__ xout,
                                                 int write_next) {
    extern __shared__ char smem[];
    float* sBias  = (float*)smem;
    float* sGamma = (float*)(smem + 512);
    float* sBeta  = (float*)(smem + 1024);
    uint32_t smem_u = smem_to_u32(smem);
    int tid = threadIdx.x;
    int wid = tid >> 5;
    int lane = tid & 31;
    int brow = blockIdx.x * 128;

    if (tid < 32) {
        *reinterpret_cast<float4*>(&sBias[tid * 4]) =
            *reinterpret_cast<const float4*>(bias + tid * 4);
        *reinterpret_cast<float4*>(&sGamma[tid * 4]) =
            *reinterpret_cast<const float4*>(gamma + tid * 4);
        *reinterpret_cast<float4*>(&sBeta[tid * 4]) =
            *reinterpret_cast<const float4*>(beta + tid * 4);
    }

    const __half* bh = g_bh + (size_t)layer * D * KTOT;

    // warp tile: 32 (m) x 64 (n)
    int wm = wid & 3;            // m0 = wm*32
    int wn = wid >> 2;           // n0 = wn*64
    int lrow = lane & 15;
    int kh16 = (lane >> 4) * 16;

    const uint32_t bBase = smem_u + 2048 + 32768;

    float acc[2][8][4];
#pragma unroll
    for (int t = 0; t < 2; t++)
#pragma unroll
        for (int q = 0; q < 8; q++)
#pragma unroll
            for (int j = 0; j < 4; j++) acc[t][q][j] = 0.f;

    auto load_A = [&](int c, int buf) {
        uint32_t base = smem_u + 2048 + buf * 16384;
        int kcol = c * 64;
#pragma unroll
        for (int it = 0; it < 4; it++) {
            int u = tid + it * 256;          // 0..1023
            int row = u >> 3;                // 0..127
            int c16 = u & 7;
            uint32_t off = row * 128 + c16 * 16;
            uint32_t sw = off ^ ((off >> 3) & 0x70);
            CP16(base + sw, &g_ah[(size_t)(brow + row) * KTOT + kcol + c16 * 8]);
        }
        asm volatile("cp.async.commit_group;" ::: "memory");
    };
    auto load_B = [&](int c) {
        int kcol = c * 64;
#pragma unroll
        for (int it = 0; it < 4; it++) {
            int u = tid + it * 256;          // 0..1023 -> full 128 rows
            int row = u >> 3;
            int c16 = u & 7;
            uint32_t off = row * 128 + c16 * 16;
            uint32_t sw = off ^ ((off >> 3) & 0x70);
            CP16(bBase + sw, &bh[(size_t)row * KTOT + kcol + c16 * 8]);
        }
        asm volatile("cp.async.commit_group;" ::: "memory");
    };

    load_A(0, 0);
    load_B(0);

    for (int c = 0; c < NCHUNK; c++) {
        asm volatile("cp.async.wait_group 0;" ::: "memory");
        __syncthreads();
        if (c + 1 < NCHUNK) load_A(c + 1, (c + 1) & 1);   // A buffer (c+1)&1 is free

        uint32_t base = smem_u + 2048 + (c & 1) * 16384;
#pragma unroll
        for (int ks = 0; ks < 4; ks++) {
            int kb = ks * 32 + kh16;
            uint32_t ah[2][4], bhf[4][4];
#pragma unroll
            for (int t = 0; t < 2; t++) {
                int row = wm * 32 + t * 16 + lrow;
                uint32_t off = row * 128 + kb;
                ldsm_x4(ah[t], base + (off ^ ((off >> 3) & 0x70)));
            }
#pragma unroll
            for (int p = 0; p < 4; p++) {
                int row = wn * 64 + p * 16 + lrow;
                uint32_t off = row * 128 + kb;
                ldsm_x4(bhf[p], bBase + (off ^ ((off >> 3) & 0x70)));
            }
#pragma unroll
            for (int t = 0; t < 2; t++)
#pragma unroll
                for (int p = 0; p < 4; p++) {
                    mma16816(acc[t][2 * p + 0], ah[t], bhf[p][0], bhf[p][2]);
                    mma16816(acc[t][2 * p + 1], ah[t], bhf[p][1], bhf[p][3]);
                }
        }
        __syncthreads();                         // all warps done with B(c)
        if (c + 1 < NCHUNK) load_B(c + 1);       // refill single B buffer
    }
    // tile smem dead after final sync -> reuse for LN partials

    float* sSum = (float*)(smem + 2048);   // [128][2]
    float* sSq  = (float*)(smem + 3072);   // [128][2]

    // ---- step 1: v = relu(acc + bias) + xin ; per-row partials ----
    float psum[2][2], psq[2][2];
#pragma unroll
    for (int t = 0; t < 2; t++) {
        int r0 = brow + wm * 32 + t * 16 + (lane >> 2);
        int r1 = r0 + 8;
        float s0 = 0.f, s1 = 0.f, q0 = 0.f, q1 = 0.f;
#pragma unroll
        for (int q = 0; q < 8; q++) {
            int col = wn * 64 + (q >> 1) * 16 + (q & 1) * 8 + 2 * (lane & 3);
            float bx = sBias[col], by = sBias[col + 1];
            float2 x0 = (r0 < N_NODES)
                ? *reinterpret_cast<const float2*>(xin + (size_t)r0 * D + col)
                : make_float2(0.f, 0.f);
            float2 x1 = (r1 < N_NODES)
                ? *reinterpret_cast<const float2*>(xin + (size_t)r1 * D + col)
                : make_float2(0.f, 0.f);
            float v0 = fmaxf(acc[t][q][0] + bx, 0.f) + x0.x;
            float v1 = fmaxf(acc[t][q][1] + by, 0.f) + x0.y;
            float v2 = fmaxf(acc[t][q][2] + bx, 0.f) + x1.x;
            float v3 = fmaxf(acc[t][q][3] + by, 0.f) + x1.y;
            acc[t][q][0] = v0; acc[t][q][1] = v1;
            acc[t][q][2] = v2; acc[t][q][3] = v3;
            s0 += v0 + v1;  q0 += v0 * v0 + v1 * v1;
            s1 += v2 + v3;  q1 += v2 * v2 + v3 * v3;
        }
        psum[t][0] = s0; psum[t][1] = s1;
        psq[t][0] = q0;  psq[t][1] = q1;
    }
    // quad reduce (4 threads share each row)
#pragma unroll
    for (int t = 0; t < 2; t++)
#pragma unroll
        for (int h = 0; h < 2; h++) {
            psum[t][h] += __shfl_xor_sync(0xFFFFFFFFu, psum[t][h], 1);
            psum[t][h] += __shfl_xor_sync(0xFFFFFFFFu, psum[t][h], 2);
            psq[t][h]  += __shfl_xor_sync(0xFFFFFFFFu, psq[t][h], 1);
            psq[t][h]  += __shfl_xor_sync(0xFFFFFFFFu, psq[t][h], 2);
        }
    if ((lane & 3) == 0) {
#pragma unroll
        for (int t = 0; t < 2; t++) {
            int m0 = wm * 32 + t * 16 + (lane >> 2);
            sSum[m0 * 2 + wn] = psum[t][0];
            sSum[(m0 + 8) * 2 + wn] = psum[t][1];
            sSq[m0 * 2 + wn] = psq[t][0];
            sSq[(m0 + 8) * 2 + wn] = psq[t][1];
        }
    }
    __syncthreads();

    // ---- step 2: LN + write xout (+ fp16 self-cols for next layer) ----
#pragma unroll
    for (int t = 0; t < 2; t++) {
        int m0 = wm * 32 + t * 16 + (lane >> 2);
#pragma unroll
        for (int h = 0; h < 2; h++) {
            int m = m0 + h * 8;
            int row = brow + m;
            if (row >= N_NODES) continue;
            float s = sSum[m * 2 + 0] + sSum[m * 2 + 1];
            float sq = sSq[m * 2 + 0] + sSq[m * 2 + 1];
            float mean = s * (1.0f / 128.0f);
            float var = sq * (1.0f / 128.0f) - mean * mean;
            float rs = rsqrtf(var + 1e-5f);
#pragma unroll
            for (int q = 0; q < 8; q++) {
                int col = wn * 64 + (q >> 1) * 16 + (q & 1) * 8 + 2 * (lane & 3);
                float o0 = (acc[t][q][2 * h + 0] - mean) * rs * sGamma[col] + sBeta[col];
                float o1 = (acc[t][q][2 * h + 1] - mean) * rs * sGamma[col + 1] + sBeta[col + 1];
                *reinterpret_cast<float2*>(xout + (size_t)row * D + col) =
                    make_float2(o0, o1);
                if (write_next) {
                    __half2 hp = __floats2half2_rn(o0, o1);
                    *reinterpret_cast<__half2*>(
                        &g_ah[(size_t)row * KTOT + 512 + col]) = hp;
                }
            }
        }
    }
}

// ---------------- host launcher ----------------
extern "C" void kernel_launch(void* const* d_in, const int* in_sizes, int n_in,
                              void* d_out, int out_size) {
    const float* x     = (const float*)d_in[0];
    const int*   ei    = (const int*)d_in[1];
    const int*   et    = (const int*)d_in[2];
    const float* W     = (const float*)d_in[3];
    const float* root  = (const float*)d_in[4];
    const float* bias  = (const float*)d_in[5];
    const float* gamma = (const float*)d_in[6];
    const float* beta  = (const float*)d_in[7];
    float* out = (float*)d_out;

    const int* src = ei;
    const int* dst = ei + N_EDGES;

    float *px1 = nullptr, *px2 = nullptr;
    cudaGetSymbolAddress((void**)&px1, g_x1);
    cudaGetSymbolAddress((void**)&px2, g_x2);

    cudaFuncSetAttribute(k_gemm, cudaFuncAttributeMaxDynamicSharedMemorySize, SMEM_DYN);

    // CSR build (edge structure is layer-invariant); g_cnt arrives zeroed
    // (static init on first run, self-cleaned by k_scan23 on every run).
    k_hist<<<(N_EDGES + 255) / 256, 256>>>(dst, et);
    int nb = (NSEG + 1023) / 1024;
    k_scan1<<<nb, 1024>>>();
    k_scan23<<<nb, 1024>>>(nb);
    k_scatter<<<(N_EDGES + 255) / 256, 256>>>(src, dst, et);

    // fused weight transpose + layer-0 self-cols
    int prep_items = NW + N_NODES * 32;
    k_prep<<<(prep_items + 255) / 256, 256>>>(W, root, x);

    const float* xin = x;
    for (int l = 0; l < NLAYER; l++) {
        k_agg<<<(N_NODES + 7) / 8, 256>>>();
        float* xout = (l == NLAYER - 1) ? out : ((l == 0) ? px1 : px2);
        k_gemm<<<NTILES, 256, SMEM_DYN>>>(l, bias + (size_t)l * D,
                                          gamma + (size_t)l * D,
                                          beta + (size_t)l * D,
                                          xin, xout,
                                          l < NLAYER - 1 ? 1 : 0);
        xin = xout;
    }
}